// round 14
// baseline (speedup 1.0000x reference)
#include <cuda_runtime.h>
#include <cuda_fp16.h>
#include <stdint.h>
#include <math.h>

#define B_DIM 256
#define K_DIM 4096

#define BM 256              // full batch per CTA
#define BN 128
#define BK 64               // K elements per stage
#define PHW 36              // A row pitch in words (64 halves + pad) — conflict-free
#define PBHW 36             // B row pitch in words (64 halves + pad) — conflict-free
#define A_STAGE_WORDS (BM * PHW)                      // 9216 w (36864 B)
#define B_STAGE_WORDS (BN * PBHW)                     // 4608 w (18432 B)
#define STAGE_WORDS (A_STAGE_WORDS + B_STAGE_WORDS)   // 13824 w (55296 B)
#define NST 3
#define NTHREADS 256        // 8 warps: 4 along M x 2 along N, warp tile 64x64
#define SPLITK1 4
#define SPLITK2 4

// scratch (allocation-free rule)
__device__ float  g_part[4 * B_DIM * K_DIM];   // split-K partials (16 MB)
__device__ __half g_xh_h[2 * B_DIM * K_DIM];   // fp16 [x ; h0]
__device__ __half g_hn_h[B_DIM * K_DIM];       // fp16 hidden state

// ---------------- helpers ----------------

__device__ __forceinline__ uint32_t pack_f16x2(float lo, float hi) {
    uint32_t d;
    asm("cvt.rn.f16x2.f32 %0, %1, %2;" : "=r"(d) : "f"(hi), "f"(lo));
    return d;
}

__device__ __forceinline__ void mma16(float c[4], const uint32_t a[4], const uint32_t b[2]) {
    asm volatile(
        "mma.sync.aligned.m16n8k16.row.col.f32.f16.f16.f32 "
        "{%0,%1,%2,%3}, {%4,%5,%6,%7}, {%8,%9}, {%0,%1,%2,%3};\n"
        : "+f"(c[0]), "+f"(c[1]), "+f"(c[2]), "+f"(c[3])
        : "r"(a[0]), "r"(a[1]), "r"(a[2]), "r"(a[3]),
          "r"(b[0]), "r"(b[1]));
}

__device__ __forceinline__ void cp_async16(void* smem_dst, const void* gsrc) {
    unsigned s = (unsigned)__cvta_generic_to_shared(smem_dst);
    asm volatile("cp.async.cg.shared.global [%0], [%1], 16;\n" :: "r"(s), "l"(gsrc));
}
__device__ __forceinline__ void cp_commit() {
    asm volatile("cp.async.commit_group;\n");
}
template <int N>
__device__ __forceinline__ void cp_wait() {
    asm volatile("cp.async.wait_group %0;\n" :: "n"(N));
}

__device__ __forceinline__ void sts128(uint32_t* p, uint32_t w0, uint32_t w1,
                                       uint32_t w2, uint32_t w3) {
    unsigned s = (unsigned)__cvta_generic_to_shared(p);
    asm volatile("st.shared.v4.b32 [%0], {%1,%2,%3,%4};"
                 :: "r"(s), "r"(w0), "r"(w1), "r"(w2), "r"(w3) : "memory");
}

// ---------------- prep: convert x,h0 to fp16 once ----------------

__global__ void __launch_bounds__(256)
prep_kernel(const float* __restrict__ x, const float* __restrict__ h0) {
    size_t e = ((size_t)blockIdx.x * 256 + threadIdx.x) * 4;
    const size_t half_n = (size_t)B_DIM * K_DIM;
    const float* src = (e < half_n) ? (x + e) : (h0 + (e - half_n));
    float4 p = *(const float4*)src;
    uint2 o;
    o.x = pack_f16x2(p.x, p.y);
    o.y = pack_f16x2(p.z, p.w);
    *(uint2*)(g_xh_h + e) = o;
}

// ---------------- GEMM (split-K partial, fp16 HMMA, fp16 B via LDG->cvt->STS) ----------------

template <int GEMM>
__global__ void __launch_bounds__(NTHREADS, 1)
gemm_splitk_kernel(const float* __restrict__ w0, const float* __restrict__ w1,
                   int KT) {
    extern __shared__ uint32_t smw[];   // 3 stages: [A 9216 w fp16][B 4608 w fp16]

    const int t = threadIdx.x;
    const int z = blockIdx.z;
    const int bx = blockIdx.x;

    // resolve split-K sources
    const __half* Ah;
    const float* Bw;
    size_t koff;
    if (GEMM == 1) {
        Ah = g_xh_h + (z >= 2 ? (size_t)B_DIM * K_DIM : 0);
        Bw = (z < 2) ? w0 : w1;
        koff = (size_t)(z & 1) * (K_DIM / 2);            // 2048
    } else {
        Ah = g_hn_h; Bw = w0;
        koff = (size_t)z * (K_DIM / SPLITK2);            // 1024
    }

    // A load geometry: 2048 vec16/stage (256 rows x 8), 8 per thread; rows step +32
    const int arow = t >> 3, avc = t & 7;
    const __half* srcA = Ah + (size_t)arow * K_DIM + koff + avc * 8;
    uint32_t* dstA = smw + arow * PHW + avc * 4;

    // B geometry: each thread owns row rB = t>>1, float cols [p*32, p*32+32)
    const int rB = t >> 1, pB = t & 1;
    const float* srcB = Bw + ((size_t)(bx * BN + rB)) * K_DIM + koff + pB * 32;
    uint32_t* dstB = smw + A_STAGE_WORDS + rB * PBHW + pB * 16;

    float acc[4][8][4];
#pragma unroll
    for (int i = 0; i < 4; i++)
#pragma unroll
        for (int j = 0; j < 8; j++)
#pragma unroll
            for (int k = 0; k < 4; k++) acc[i][j][k] = 0.0f;

    const int lane = t & 31, warp = t >> 5;
    const int wm = (warp >> 1) * 64;    // 4 warps along M
    const int wn = (warp & 1) * 64;     // 2 warps along N (64 cols each)
    const int g = lane >> 2, tc = lane & 3;

    float4 breg[8];   // 32 floats: B(kt+2) in flight

    // ---- prologue ----
    // B(0): LDG + cvt + STS into stage 0
    {
        float4 f[8];
#pragma unroll
        for (int c = 0; c < 8; c++) f[c] = *(const float4*)(srcB + c * 4);
#pragma unroll
        for (int c = 0; c < 4; c++) {
            uint32_t q0 = pack_f16x2(f[2 * c].x, f[2 * c].y);
            uint32_t q1 = pack_f16x2(f[2 * c].z, f[2 * c].w);
            uint32_t q2 = pack_f16x2(f[2 * c + 1].x, f[2 * c + 1].y);
            uint32_t q3 = pack_f16x2(f[2 * c + 1].z, f[2 * c + 1].w);
            sts128(dstB + c * 4, q0, q1, q2, q3);
        }
    }
    // B(1): LDG into breg (STS'd during iter 0)
    if (KT > 1) {
#pragma unroll
        for (int c = 0; c < 8; c++) breg[c] = *(const float4*)(srcB + BK + c * 4);
    }
    // A stages 0,1 via cp.async
#pragma unroll
    for (int s = 0; s < 2; s++) {
        uint32_t* da = dstA + s * STAGE_WORDS;
        size_t ko = (size_t)s * BK;
#pragma unroll
        for (int i = 0; i < 8; i++) cp_async16(da + i * 32 * PHW, srcA + ko + (size_t)i * 32 * K_DIM);
        cp_commit();
    }

#pragma unroll 1
    for (int kt = 0; kt < KT; kt++) {
        // A stage kt ready (leave A(kt+1) in flight when it exists)
        if (kt + 1 < KT) cp_wait<1>(); else cp_wait<0>();
        __syncthreads();   // A deposits + last iter's B STS visible; compute kt-1 done

        // issue LDG for B(kt+2)
        float4 bnext[8];
        if (kt + 2 < KT) {
            size_t ko = (size_t)(kt + 2) * BK;
#pragma unroll
            for (int c = 0; c < 8; c++) bnext[c] = *(const float4*)(srcB + ko + c * 4);
        }
        // cvt + STS B(kt+1) (loaded last iteration, long arrived) -> stage (kt+1)%3
        if (kt + 1 < KT) {
            uint32_t* db = dstB + ((kt + 1) % NST) * STAGE_WORDS;
#pragma unroll
            for (int c = 0; c < 4; c++) {
                uint32_t q0 = pack_f16x2(breg[2 * c].x, breg[2 * c].y);
                uint32_t q1 = pack_f16x2(breg[2 * c].z, breg[2 * c].w);
                uint32_t q2 = pack_f16x2(breg[2 * c + 1].x, breg[2 * c + 1].y);
                uint32_t q3 = pack_f16x2(breg[2 * c + 1].z, breg[2 * c + 1].w);
                sts128(db + c * 4, q0, q1, q2, q3);
            }
        }
        // A cp.async for stage kt+2 (buffer freed by this iteration's barrier)
        if (kt + 2 < KT) {
            uint32_t* da = dstA + ((kt + 2) % NST) * STAGE_WORDS;
            size_t ko = (size_t)(kt + 2) * BK;
#pragma unroll
            for (int i = 0; i < 8; i++) cp_async16(da + i * 32 * PHW, srcA + ko + (size_t)i * 32 * K_DIM);
            cp_commit();
        }

        const uint32_t* Aw = smw + (kt % NST) * STAGE_WORDS;
        const uint32_t* Bh = Aw + A_STAGE_WORDS;
#pragma unroll
        for (int ks2 = 0; ks2 < 4; ks2++) {    // four k16 steps per BK=64
            uint32_t a[4][4];
#pragma unroll
            for (int mi = 0; mi < 4; mi++) {
                int r = wm + mi * 16 + g;
                int base = ks2 * 8 + tc;
                a[mi][0] = Aw[r * PHW + base];
                a[mi][1] = Aw[(r + 8) * PHW + base];
                a[mi][2] = Aw[r * PHW + base + 4];
                a[mi][3] = Aw[(r + 8) * PHW + base + 4];
            }
            uint32_t b[8][2];
#pragma unroll
            for (int ni = 0; ni < 8; ni++) {
                int r = wn + ni * 8 + g;
                b[ni][0] = Bh[r * PBHW + ks2 * 8 + tc];
                b[ni][1] = Bh[r * PBHW + ks2 * 8 + tc + 4];
            }
#pragma unroll
            for (int mi = 0; mi < 4; mi++)
#pragma unroll
                for (int ni = 0; ni < 8; ni++)
                    mma16(acc[mi][ni], a[mi], b[ni]);
        }

        // carry B(kt+2) registers into next iteration
        if (kt + 2 < KT) {
#pragma unroll
            for (int c = 0; c < 8; c++) breg[c] = bnext[c];
        }
        // no bottom barrier: next iteration's top barrier orders buffer reuse
    }

    // write partial tile
    float* part = g_part + (size_t)z * (B_DIM * K_DIM);
#pragma unroll
    for (int mi = 0; mi < 4; mi++) {
#pragma unroll
        for (int ni = 0; ni < 8; ni++) {
            int gr = wm + mi * 16 + g;
            int gc = bx * BN + wn + ni * 8 + tc * 2;
            size_t o0 = (size_t)gr * K_DIM + gc;
            size_t o2 = (size_t)(gr + 8) * K_DIM + gc;
            *(float2*)(part + o0) = make_float2(acc[mi][ni][0], acc[mi][ni][1]);
            *(float2*)(part + o2) = make_float2(acc[mi][ni][2], acc[mi][ni][3]);
        }
    }
}

// ---------------- reduce1: hn = tanh(sum partials + bih + bhh) ----------------

__global__ void __launch_bounds__(256)
reduce1_kernel(const float* __restrict__ bih, const float* __restrict__ bhh,
               float* __restrict__ hn_out) {
    size_t e = ((size_t)blockIdx.x * 256 + threadIdx.x) * 4;
    int col = (int)(e & (K_DIM - 1));
    float4 p0 = *(const float4*)(g_part + e);
    float4 p1 = *(const float4*)(g_part + (size_t)1 * B_DIM * K_DIM + e);
    float4 p2 = *(const float4*)(g_part + (size_t)2 * B_DIM * K_DIM + e);
    float4 p3 = *(const float4*)(g_part + (size_t)3 * B_DIM * K_DIM + e);
    float4 ba = *(const float4*)(bih + col);
    float4 bb = *(const float4*)(bhh + col);
    float t0 = tanhf(p0.x + p1.x + p2.x + p3.x + ba.x + bb.x);
    float t1 = tanhf(p0.y + p1.y + p2.y + p3.y + ba.y + bb.y);
    float t2 = tanhf(p0.z + p1.z + p2.z + p3.z + ba.z + bb.z);
    float t3 = tanhf(p0.w + p1.w + p2.w + p3.w + ba.w + bb.w);
    *(float4*)(hn_out + e) = make_float4(t0, t1, t2, t3);
    uint2 o;
    o.x = pack_f16x2(t0, t1);
    o.y = pack_f16x2(t2, t3);
    *(uint2*)(g_hn_h + e) = o;
}

// ---------------- softmax (fuses GEMM2 split-K reduce + bias) ----------------

#define SMT 512

__global__ void __launch_bounds__(SMT)
softmax_kernel(const float* __restrict__ blin, float* __restrict__ probs) {
    __shared__ float sl[K_DIM];
    __shared__ float red[SMT];
    const int row = blockIdx.x, tid = threadIdx.x;
    const size_t rb = (size_t)row * K_DIM;

    float m = -1e30f;
    for (int i = tid * 4; i < K_DIM; i += SMT * 4) {
        float4 p0 = *(const float4*)(g_part + rb + i);
        float4 p1 = *(const float4*)(g_part + (size_t)1 * B_DIM * K_DIM + rb + i);
        float4 p2 = *(const float4*)(g_part + (size_t)2 * B_DIM * K_DIM + rb + i);
        float4 p3 = *(const float4*)(g_part + (size_t)3 * B_DIM * K_DIM + rb + i);
        float4 b  = *(const float4*)(blin + i);
        float v0 = p0.x + p1.x + p2.x + p3.x + b.x;
        float v1 = p0.y + p1.y + p2.y + p3.y + b.y;
        float v2 = p0.z + p1.z + p2.z + p3.z + b.z;
        float v3 = p0.w + p1.w + p2.w + p3.w + b.w;
        *(float4*)(sl + i) = make_float4(v0, v1, v2, v3);
        m = fmaxf(m, fmaxf(fmaxf(v0, v1), fmaxf(v2, v3)));
    }
    red[tid] = m;
    __syncthreads();
    for (int s = SMT / 2; s > 0; s >>= 1) {
        if (tid < s) red[tid] = fmaxf(red[tid], red[tid + s]);
        __syncthreads();
    }
    m = red[0];
    __syncthreads();

    float sum = 0.0f;
    for (int i = tid; i < K_DIM; i += SMT) sum += expf(sl[i] - m);
    red[tid] = sum;
    __syncthreads();
    for (int s = SMT / 2; s > 0; s >>= 1) {
        if (tid < s) red[tid] += red[tid + s];
        __syncthreads();
    }
    float inv = 1.0f / red[0];

    for (int i = tid; i < K_DIM; i += SMT)
        probs[rb + i] = expf(sl[i] - m) * inv;
}

// ---------------- launch ----------------

extern "C" void kernel_launch(void* const* d_in, const int* in_sizes, int n_in,
                              void* d_out, int out_size) {
    const float* x    = (const float*)d_in[0];
    const float* h0   = (const float*)d_in[1];
    const float* wih  = (const float*)d_in[2];
    const float* bih  = (const float*)d_in[3];
    const float* whh  = (const float*)d_in[4];
    const float* bhh  = (const float*)d_in[5];
    const float* wlin = (const float*)d_in[6];
    const float* blin = (const float*)d_in[7];

    float* out = (float*)d_out;
    float* probs_out = out;
    float* hn_out    = out + (size_t)B_DIM * K_DIM;

    const int dyn = NST * STAGE_WORDS * sizeof(uint32_t);   // 165888 B
    cudaFuncSetAttribute(gemm_splitk_kernel<1>, cudaFuncAttributeMaxDynamicSharedMemorySize, dyn);
    cudaFuncSetAttribute(gemm_splitk_kernel<2>, cudaFuncAttributeMaxDynamicSharedMemorySize, dyn);

    // convert x,h0 to fp16 once
    prep_kernel<<<(2 * B_DIM * K_DIM) / (256 * 4), 256>>>(x, h0);

    // GEMM1: partials of x@wih^T + h0@whh^T (fused K=8192, split 4)
    dim3 grid1(K_DIM / BN, 1, SPLITK1);    // (32,1,4) = 128 CTAs
    gemm_splitk_kernel<1><<<grid1, NTHREADS, dyn>>>(wih, whh, (K_DIM / 2) / BK);  // KT=32

    reduce1_kernel<<<(B_DIM * K_DIM) / (256 * 4), 256>>>(bih, bhh, hn_out);

    // GEMM2: partials of hn@wlin^T (K=4096, split 4)
    dim3 grid2(K_DIM / BN, 1, SPLITK2);
    gemm_splitk_kernel<2><<<grid2, NTHREADS, dyn>>>(wlin, nullptr, (K_DIM / SPLITK2) / BK);  // KT=16

    softmax_kernel<<<B_DIM, SMT>>>(blin, probs_out);
}

// round 15
// speedup vs baseline: 1.4291x; 1.4291x over previous
#include <cuda_runtime.h>
#include <cuda_fp16.h>
#include <stdint.h>
#include <math.h>

#define B_DIM 256
#define K_DIM 4096

#define BM 256              // full batch per CTA
#define BK 64               // K elements per stage
#define PHW 36              // A row pitch in words (64 halves + pad) — conflict-free
#define PBF 72              // B row pitch in floats (64 floats + pad) — conflict-free
#define NST 3
#define NTHREADS 256
#define SPLITK1 4           // GEMM1: fused K=8192 -> KT=32
#define SPLITK2 2           // GEMM2: K=4096 -> KT=32

// GEMM1 tile: BN1=128
#define BN1 128
#define A_STAGE_WORDS (BM * PHW)                        // 9216 w
#define B1_STAGE_WORDS (BN1 * PBF)                      // 9216 w
#define STAGE1_WORDS (A_STAGE_WORDS + B1_STAGE_WORDS)   // 18432 w (73728 B)
// GEMM2 tile: BN2=64
#define BN2 64
#define B2_STAGE_WORDS (BN2 * PBF)                      // 4608 w
#define STAGE2_WORDS (A_STAGE_WORDS + B2_STAGE_WORDS)   // 13824 w (55296 B)

// scratch (allocation-free rule)
__device__ float  g_part[4 * B_DIM * K_DIM];   // split-K partials (16 MB)
__device__ __half g_xh_h[2 * B_DIM * K_DIM];   // fp16 [x ; h0]
__device__ __half g_hn_h[B_DIM * K_DIM];       // fp16 hidden state

// ---------------- helpers ----------------

__device__ __forceinline__ uint32_t pack_f16x2(float lo, float hi) {
    uint32_t d;
    asm("cvt.rn.f16x2.f32 %0, %1, %2;" : "=r"(d) : "f"(hi), "f"(lo));
    return d;
}

__device__ __forceinline__ void mma16(float c[4], const uint32_t a[4], const uint32_t b[2]) {
    asm volatile(
        "mma.sync.aligned.m16n8k16.row.col.f32.f16.f16.f32 "
        "{%0,%1,%2,%3}, {%4,%5,%6,%7}, {%8,%9}, {%0,%1,%2,%3};\n"
        : "+f"(c[0]), "+f"(c[1]), "+f"(c[2]), "+f"(c[3])
        : "r"(a[0]), "r"(a[1]), "r"(a[2]), "r"(a[3]),
          "r"(b[0]), "r"(b[1]));
}

__device__ __forceinline__ void cp_async16(void* smem_dst, const void* gsrc) {
    unsigned s = (unsigned)__cvta_generic_to_shared(smem_dst);
    asm volatile("cp.async.cg.shared.global [%0], [%1], 16;\n" :: "r"(s), "l"(gsrc));
}
__device__ __forceinline__ void cp_commit() {
    asm volatile("cp.async.commit_group;\n");
}
template <int N>
__device__ __forceinline__ void cp_wait() {
    asm volatile("cp.async.wait_group %0;\n" :: "n"(N));
}

// ---------------- prep: convert x,h0 to fp16 once ----------------

__global__ void __launch_bounds__(256)
prep_kernel(const float* __restrict__ x, const float* __restrict__ h0) {
    size_t e = ((size_t)blockIdx.x * 256 + threadIdx.x) * 4;
    const size_t half_n = (size_t)B_DIM * K_DIM;
    const float* src = (e < half_n) ? (x + e) : (h0 + (e - half_n));
    float4 p = *(const float4*)src;
    uint2 o;
    o.x = pack_f16x2(p.x, p.y);
    o.y = pack_f16x2(p.z, p.w);
    *(uint2*)(g_xh_h + e) = o;
}

// ---------------- GEMM1 (BN=128, warp 64x64, KT=32) — unchanged from R12 ----------------

__global__ void __launch_bounds__(NTHREADS, 1)
gemm1_kernel(const float* __restrict__ w0, const float* __restrict__ w1, int KT) {
    extern __shared__ uint32_t smw[];

    const int t = threadIdx.x;
    const int z = blockIdx.z;
    const int bx = blockIdx.x;

    const __half* Ah = g_xh_h + (z >= 2 ? (size_t)B_DIM * K_DIM : 0);
    const float* Bw = (z < 2) ? w0 : w1;
    size_t koff = (size_t)(z & 1) * (K_DIM / 2);

    const int arow = t >> 3, avc = t & 7;
    const __half* srcA = Ah + (size_t)arow * K_DIM + koff + avc * 8;
    uint32_t* dstA = smw + arow * PHW + avc * 4;
    const int brow = t >> 4, bvc = t & 15;
    const float* srcB = Bw + ((size_t)(bx * BN1 + brow)) * K_DIM + koff + bvc * 4;
    uint32_t* dstB = smw + A_STAGE_WORDS + brow * PBF + bvc * 4;

    float acc[4][8][4];
#pragma unroll
    for (int i = 0; i < 4; i++)
#pragma unroll
        for (int j = 0; j < 8; j++)
#pragma unroll
            for (int k = 0; k < 4; k++) acc[i][j][k] = 0.0f;

    const int lane = t & 31, warp = t >> 5;
    const int wm = (warp >> 1) * 64;
    const int wn = (warp & 1) * 64;
    const int g = lane >> 2, tc = lane & 3;

#pragma unroll
    for (int s = 0; s < 2; s++) {
        uint32_t* da = dstA + s * STAGE1_WORDS;
        uint32_t* db = dstB + s * STAGE1_WORDS;
        size_t ko = (size_t)s * BK;
#pragma unroll
        for (int i = 0; i < 8; i++) cp_async16(da + i * 32 * PHW, srcA + ko + (size_t)i * 32 * K_DIM);
#pragma unroll
        for (int i = 0; i < 8; i++) cp_async16(db + i * 16 * PBF, srcB + ko + (size_t)i * 16 * K_DIM);
        cp_commit();
    }

#pragma unroll 1
    for (int kt = 0; kt < KT; kt++) {
        if (kt + 1 < KT) cp_wait<1>(); else cp_wait<0>();
        __syncthreads();

        if (kt + 2 < KT) {
            const int sl = (kt + 2) % NST;
            uint32_t* da = dstA + sl * STAGE1_WORDS;
            uint32_t* db = dstB + sl * STAGE1_WORDS;
            size_t ko = (size_t)(kt + 2) * BK;
#pragma unroll
            for (int i = 0; i < 8; i++) cp_async16(da + i * 32 * PHW, srcA + ko + (size_t)i * 32 * K_DIM);
#pragma unroll
            for (int i = 0; i < 8; i++) cp_async16(db + i * 16 * PBF, srcB + ko + (size_t)i * 16 * K_DIM);
            cp_commit();
        }

        const uint32_t* Aw = smw + (kt % NST) * STAGE1_WORDS;
        const float*    Bf = (const float*)(Aw + A_STAGE_WORDS);
#pragma unroll
        for (int ks2 = 0; ks2 < 4; ks2++) {
            uint32_t a[4][4];
#pragma unroll
            for (int mi = 0; mi < 4; mi++) {
                int r = wm + mi * 16 + g;
                int base = ks2 * 8 + tc;
                a[mi][0] = Aw[r * PHW + base];
                a[mi][1] = Aw[(r + 8) * PHW + base];
                a[mi][2] = Aw[r * PHW + base + 4];
                a[mi][3] = Aw[(r + 8) * PHW + base + 4];
            }
            uint32_t b[8][2];
#pragma unroll
            for (int ni = 0; ni < 8; ni++) {
                int r = wn + ni * 8 + g;
                const float* bp = Bf + r * PBF + ks2 * 16 + 2 * tc;
                float2 p0 = *(const float2*)bp;
                float2 p1 = *(const float2*)(bp + 8);
                b[ni][0] = pack_f16x2(p0.x, p0.y);
                b[ni][1] = pack_f16x2(p1.x, p1.y);
            }
#pragma unroll
            for (int mi = 0; mi < 4; mi++)
#pragma unroll
                for (int ni = 0; ni < 8; ni++)
                    mma16(acc[mi][ni], a[mi], b[ni]);
        }
    }

    float* part = g_part + (size_t)z * (B_DIM * K_DIM);
#pragma unroll
    for (int mi = 0; mi < 4; mi++) {
#pragma unroll
        for (int ni = 0; ni < 8; ni++) {
            int gr = wm + mi * 16 + g;
            int gc = bx * BN1 + wn + ni * 8 + tc * 2;
            size_t o0 = (size_t)gr * K_DIM + gc;
            size_t o2 = (size_t)(gr + 8) * K_DIM + gc;
            *(float2*)(part + o0) = make_float2(acc[mi][ni][0], acc[mi][ni][1]);
            *(float2*)(part + o2) = make_float2(acc[mi][ni][2], acc[mi][ni][3]);
        }
    }
}

// ---------------- GEMM2 (BN=64, warp 64x32, SPLITK=2 -> KT=32) ----------------

__global__ void __launch_bounds__(NTHREADS, 1)
gemm2_kernel(const float* __restrict__ w0, int KT) {
    extern __shared__ uint32_t smw[];

    const int t = threadIdx.x;
    const int z = blockIdx.z;
    const int bx = blockIdx.x;

    const __half* Ah = g_hn_h;
    const float* Bw = w0;
    size_t koff = (size_t)z * (K_DIM / SPLITK2);     // 0 or 2048

    // A: 2048 vec16/stage, 8 per thread; rows step +32
    const int arow = t >> 3, avc = t & 7;
    const __half* srcA = Ah + (size_t)arow * K_DIM + koff + avc * 8;
    uint32_t* dstA = smw + arow * PHW + avc * 4;
    // B: 64 rows x 16 vec16 = 1024 vec16/stage, 4 per thread; rows step +16
    const int brow = t >> 4, bvc = t & 15;
    const float* srcB = Bw + ((size_t)(bx * BN2 + brow)) * K_DIM + koff + bvc * 4;
    uint32_t* dstB = smw + A_STAGE_WORDS + brow * PBF + bvc * 4;

    float acc[4][4][4];
#pragma unroll
    for (int i = 0; i < 4; i++)
#pragma unroll
        for (int j = 0; j < 4; j++)
#pragma unroll
            for (int k = 0; k < 4; k++) acc[i][j][k] = 0.0f;

    const int lane = t & 31, warp = t >> 5;
    const int wm = (warp >> 1) * 64;    // 4 warps along M
    const int wn = (warp & 1) * 32;     // 2 warps along N
    const int g = lane >> 2, tc = lane & 3;

#pragma unroll
    for (int s = 0; s < 2; s++) {
        uint32_t* da = dstA + s * STAGE2_WORDS;
        uint32_t* db = dstB + s * STAGE2_WORDS;
        size_t ko = (size_t)s * BK;
#pragma unroll
        for (int i = 0; i < 8; i++) cp_async16(da + i * 32 * PHW, srcA + ko + (size_t)i * 32 * K_DIM);
#pragma unroll
        for (int i = 0; i < 4; i++) cp_async16(db + i * 16 * PBF, srcB + ko + (size_t)i * 16 * K_DIM);
        cp_commit();
    }

#pragma unroll 1
    for (int kt = 0; kt < KT; kt++) {
        if (kt + 1 < KT) cp_wait<1>(); else cp_wait<0>();
        __syncthreads();

        if (kt + 2 < KT) {
            const int sl = (kt + 2) % NST;
            uint32_t* da = dstA + sl * STAGE2_WORDS;
            uint32_t* db = dstB + sl * STAGE2_WORDS;
            size_t ko = (size_t)(kt + 2) * BK;
#pragma unroll
            for (int i = 0; i < 8; i++) cp_async16(da + i * 32 * PHW, srcA + ko + (size_t)i * 32 * K_DIM);
#pragma unroll
            for (int i = 0; i < 4; i++) cp_async16(db + i * 16 * PBF, srcB + ko + (size_t)i * 16 * K_DIM);
            cp_commit();
        }

        const uint32_t* Aw = smw + (kt % NST) * STAGE2_WORDS;
        const float*    Bf = (const float*)(Aw + A_STAGE_WORDS);
#pragma unroll
        for (int ks2 = 0; ks2 < 4; ks2++) {
            uint32_t a[4][4];
#pragma unroll
            for (int mi = 0; mi < 4; mi++) {
                int r = wm + mi * 16 + g;
                int base = ks2 * 8 + tc;
                a[mi][0] = Aw[r * PHW + base];
                a[mi][1] = Aw[(r + 8) * PHW + base];
                a[mi][2] = Aw[r * PHW + base + 4];
                a[mi][3] = Aw[(r + 8) * PHW + base + 4];
            }
            uint32_t b[4][2];
#pragma unroll
            for (int ni = 0; ni < 4; ni++) {
                int r = wn + ni * 8 + g;
                const float* bp = Bf + r * PBF + ks2 * 16 + 2 * tc;
                float2 p0 = *(const float2*)bp;
                float2 p1 = *(const float2*)(bp + 8);
                b[ni][0] = pack_f16x2(p0.x, p0.y);
                b[ni][1] = pack_f16x2(p1.x, p1.y);
            }
#pragma unroll
            for (int mi = 0; mi < 4; mi++)
#pragma unroll
                for (int ni = 0; ni < 4; ni++)
                    mma16(acc[mi][ni], a[mi], b[ni]);
        }
    }

    float* part = g_part + (size_t)z * (B_DIM * K_DIM);
#pragma unroll
    for (int mi = 0; mi < 4; mi++) {
#pragma unroll
        for (int ni = 0; ni < 4; ni++) {
            int gr = wm + mi * 16 + g;
            int gc = bx * BN2 + wn + ni * 8 + tc * 2;
            size_t o0 = (size_t)gr * K_DIM + gc;
            size_t o2 = (size_t)(gr + 8) * K_DIM + gc;
            *(float2*)(part + o0) = make_float2(acc[mi][ni][0], acc[mi][ni][1]);
            *(float2*)(part + o2) = make_float2(acc[mi][ni][2], acc[mi][ni][3]);
        }
    }
}

// ---------------- reduce1: hn = tanh(sum of 4 partials + bih + bhh) ----------------

__global__ void __launch_bounds__(256)
reduce1_kernel(const float* __restrict__ bih, const float* __restrict__ bhh,
               float* __restrict__ hn_out) {
    size_t e = ((size_t)blockIdx.x * 256 + threadIdx.x) * 4;
    int col = (int)(e & (K_DIM - 1));
    float4 p0 = *(const float4*)(g_part + e);
    float4 p1 = *(const float4*)(g_part + (size_t)1 * B_DIM * K_DIM + e);
    float4 p2 = *(const float4*)(g_part + (size_t)2 * B_DIM * K_DIM + e);
    float4 p3 = *(const float4*)(g_part + (size_t)3 * B_DIM * K_DIM + e);
    float4 ba = *(const float4*)(bih + col);
    float4 bb = *(const float4*)(bhh + col);
    float t0 = tanhf(p0.x + p1.x + p2.x + p3.x + ba.x + bb.x);
    float t1 = tanhf(p0.y + p1.y + p2.y + p3.y + ba.y + bb.y);
    float t2 = tanhf(p0.z + p1.z + p2.z + p3.z + ba.z + bb.z);
    float t3 = tanhf(p0.w + p1.w + p2.w + p3.w + ba.w + bb.w);
    *(float4*)(hn_out + e) = make_float4(t0, t1, t2, t3);
    uint2 o;
    o.x = pack_f16x2(t0, t1);
    o.y = pack_f16x2(t2, t3);
    *(uint2*)(g_hn_h + e) = o;
}

// ---------------- softmax (fuses GEMM2's 2-way split-K reduce + bias) ----------------

#define SMT 512

__global__ void __launch_bounds__(SMT)
softmax_kernel(const float* __restrict__ blin, float* __restrict__ probs) {
    __shared__ float sl[K_DIM];
    __shared__ float red[SMT];
    const int row = blockIdx.x, tid = threadIdx.x;
    const size_t rb = (size_t)row * K_DIM;

    float m = -1e30f;
    for (int i = tid * 4; i < K_DIM; i += SMT * 4) {
        float4 p0 = *(const float4*)(g_part + rb + i);
        float4 p1 = *(const float4*)(g_part + (size_t)1 * B_DIM * K_DIM + rb + i);
        float4 b  = *(const float4*)(blin + i);
        float v0 = p0.x + p1.x + b.x;
        float v1 = p0.y + p1.y + b.y;
        float v2 = p0.z + p1.z + b.z;
        float v3 = p0.w + p1.w + b.w;
        *(float4*)(sl + i) = make_float4(v0, v1, v2, v3);
        m = fmaxf(m, fmaxf(fmaxf(v0, v1), fmaxf(v2, v3)));
    }
    red[tid] = m;
    __syncthreads();
    for (int s = SMT / 2; s > 0; s >>= 1) {
        if (tid < s) red[tid] = fmaxf(red[tid], red[tid + s]);
        __syncthreads();
    }
    m = red[0];
    __syncthreads();

    float sum = 0.0f;
    for (int i = tid; i < K_DIM; i += SMT) sum += expf(sl[i] - m);
    red[tid] = sum;
    __syncthreads();
    for (int s = SMT / 2; s > 0; s >>= 1) {
        if (tid < s) red[tid] += red[tid + s];
        __syncthreads();
    }
    float inv = 1.0f / red[0];

    for (int i = tid; i < K_DIM; i += SMT)
        probs[rb + i] = expf(sl[i] - m) * inv;
}

// ---------------- launch ----------------

extern "C" void kernel_launch(void* const* d_in, const int* in_sizes, int n_in,
                              void* d_out, int out_size) {
    const float* x    = (const float*)d_in[0];
    const float* h0   = (const float*)d_in[1];
    const float* wih  = (const float*)d_in[2];
    const float* bih  = (const float*)d_in[3];
    const float* whh  = (const float*)d_in[4];
    const float* bhh  = (const float*)d_in[5];
    const float* wlin = (const float*)d_in[6];
    const float* blin = (const float*)d_in[7];

    float* out = (float*)d_out;
    float* probs_out = out;
    float* hn_out    = out + (size_t)B_DIM * K_DIM;

    const int dyn1 = NST * STAGE1_WORDS * sizeof(uint32_t);   // 221184 B
    const int dyn2 = NST * STAGE2_WORDS * sizeof(uint32_t);   // 165888 B
    cudaFuncSetAttribute(gemm1_kernel, cudaFuncAttributeMaxDynamicSharedMemorySize, dyn1);
    cudaFuncSetAttribute(gemm2_kernel, cudaFuncAttributeMaxDynamicSharedMemorySize, dyn2);

    // convert x,h0 to fp16 once
    prep_kernel<<<(2 * B_DIM * K_DIM) / (256 * 4), 256>>>(x, h0);

    // GEMM1: partials of x@wih^T + h0@whh^T (fused K=8192, split 4, KT=32)
    dim3 grid1(K_DIM / BN1, 1, SPLITK1);    // (32,1,4) = 128 CTAs
    gemm1_kernel<<<grid1, NTHREADS, dyn1>>>(wih, whh, (K_DIM / 2) / BK);

    reduce1_kernel<<<(B_DIM * K_DIM) / (256 * 4), 256>>>(bih, bhh, hn_out);

    // GEMM2: partials of hn@wlin^T (K=4096, split 2, KT=32)
    dim3 grid2(K_DIM / BN2, 1, SPLITK2);    // (64,1,2) = 128 CTAs
    gemm2_kernel<<<grid2, NTHREADS, dyn2>>>(wlin, (K_DIM / SPLITK2) / BK);

    softmax_kernel<<<B_DIM, SMT>>>(blin, probs_out);
}

// round 16
// speedup vs baseline: 1.4305x; 1.0010x over previous
#include <cuda_runtime.h>
#include <cuda_fp16.h>
#include <stdint.h>
#include <math.h>

#define B_DIM 256
#define K_DIM 4096

#define BM 128              // CTA tile rows
#define BN 128              // CTA tile cols
#define BK 32               // K elements per stage
#define PHW 20              // A row pitch in words (32 halves + pad) — conflict-free (R8)
#define PBF 40              // B row pitch in floats (32 floats + pad) — conflict-free (R8)
#define A_STAGE_WORDS (BM * PHW)                      // 2560 w
#define B_STAGE_WORDS (BN * PBF)                      // 5120 w
#define STAGE_WORDS (A_STAGE_WORDS + B_STAGE_WORDS)   // 7680 w (30720 B)
#define NST 3
#define NTHREADS 128        // 4 warps: 2 along M x 2 along N, warp tile 64x64
#define SPLITK 4

// scratch (allocation-free rule)
__device__ float  g_part[4 * B_DIM * K_DIM];   // split-K partials (16 MB)
__device__ __half g_xh_h[2 * B_DIM * K_DIM];   // fp16 [x ; h0]
__device__ __half g_hn_h[B_DIM * K_DIM];       // fp16 hidden state

// ---------------- helpers ----------------

__device__ __forceinline__ uint32_t pack_f16x2(float lo, float hi) {
    uint32_t d;
    asm("cvt.rn.f16x2.f32 %0, %1, %2;" : "=r"(d) : "f"(hi), "f"(lo));
    return d;
}

__device__ __forceinline__ void mma16(float c[4], const uint32_t a[4], const uint32_t b[2]) {
    asm volatile(
        "mma.sync.aligned.m16n8k16.row.col.f32.f16.f16.f32 "
        "{%0,%1,%2,%3}, {%4,%5,%6,%7}, {%8,%9}, {%0,%1,%2,%3};\n"
        : "+f"(c[0]), "+f"(c[1]), "+f"(c[2]), "+f"(c[3])
        : "r"(a[0]), "r"(a[1]), "r"(a[2]), "r"(a[3]),
          "r"(b[0]), "r"(b[1]));
}

__device__ __forceinline__ void cp_async16(void* smem_dst, const void* gsrc) {
    unsigned s = (unsigned)__cvta_generic_to_shared(smem_dst);
    asm volatile("cp.async.cg.shared.global [%0], [%1], 16;\n" :: "r"(s), "l"(gsrc));
}
__device__ __forceinline__ void cp_commit() {
    asm volatile("cp.async.commit_group;\n");
}
template <int N>
__device__ __forceinline__ void cp_wait() {
    asm volatile("cp.async.wait_group %0;\n" :: "n"(N));
}

// ---------------- prep: convert x,h0 to fp16 once ----------------

__global__ void __launch_bounds__(256)
prep_kernel(const float* __restrict__ x, const float* __restrict__ h0) {
    size_t e = ((size_t)blockIdx.x * 256 + threadIdx.x) * 4;
    const size_t half_n = (size_t)B_DIM * K_DIM;
    const float* src = (e < half_n) ? (x + e) : (h0 + (e - half_n));
    float4 p = *(const float4*)src;
    uint2 o;
    o.x = pack_f16x2(p.x, p.y);
    o.y = pack_f16x2(p.z, p.w);
    *(uint2*)(g_xh_h + e) = o;
}

// ---------------- GEMM (split-K partial, fp16 HMMA, 128x128 CTA, warp 64x64) ----------------

template <int GEMM>
__global__ void __launch_bounds__(NTHREADS, 2)
gemm_splitk_kernel(const float* __restrict__ w0, const float* __restrict__ w1,
                   int KT) {
    extern __shared__ uint32_t smw[];   // 3 stages: [A 2560 w fp16][B 5120 w fp32]

    const int t = threadIdx.x;
    const int z = blockIdx.z;
    const int bx = blockIdx.x;
    const int by = blockIdx.y;

    // resolve split-K sources
    const __half* Ah;
    const float* Bw;
    size_t koff;
    if (GEMM == 1) {
        Ah = g_xh_h + (z >= 2 ? (size_t)B_DIM * K_DIM : 0);
        Bw = (z < 2) ? w0 : w1;
        koff = (size_t)(z & 1) * (K_DIM / 2);            // 0 or 2048; KT=64
    } else {
        Ah = g_hn_h; Bw = w0;
        koff = (size_t)z * (K_DIM / SPLITK);             // z*1024; KT=32
    }

    // load geometry (128 threads)
    // A: 512 vec16/stage (128 rows x 4), 4 per thread; rows step +32
    const int arow = t >> 2, avc = t & 3;
    const __half* srcA = Ah + (size_t)(by * BM + arow) * K_DIM + koff + avc * 8;
    uint32_t* dstA = smw + arow * PHW + avc * 4;
    // B: 1024 vec16/stage (128 rows x 8), 8 per thread; rows step +16
    const int brow = t >> 3, bvc = t & 7;
    const float* srcB = Bw + ((size_t)(bx * BN + brow)) * K_DIM + koff + bvc * 4;
    uint32_t* dstB = smw + A_STAGE_WORDS + brow * PBF + bvc * 4;

    float acc[4][8][4];
#pragma unroll
    for (int i = 0; i < 4; i++)
#pragma unroll
        for (int j = 0; j < 8; j++)
#pragma unroll
            for (int k = 0; k < 4; k++) acc[i][j][k] = 0.0f;

    const int lane = t & 31, warp = t >> 5;
    const int wm = (warp >> 1) * 64;    // 2 warps along M
    const int wn = (warp & 1) * 64;     // 2 warps along N
    const int g = lane >> 2, tc = lane & 3;

    // prologue: stages 0,1
#pragma unroll
    for (int s = 0; s < 2; s++) {
        uint32_t* da = dstA + s * STAGE_WORDS;
        uint32_t* db = dstB + s * STAGE_WORDS;
        size_t ko = (size_t)s * BK;
#pragma unroll
        for (int i = 0; i < 4; i++) cp_async16(da + i * 32 * PHW, srcA + ko + (size_t)i * 32 * K_DIM);
#pragma unroll
        for (int i = 0; i < 8; i++) cp_async16(db + i * 16 * PBF, srcB + ko + (size_t)i * 16 * K_DIM);
        cp_commit();
    }

#pragma unroll 1
    for (int kt = 0; kt < KT; kt++) {
        if (kt + 1 < KT) cp_wait<1>(); else cp_wait<0>();
        __syncthreads();   // deposits for stage kt visible; compute kt-1 done
                           // -> buffer (kt+2)%3 (consumed at kt-1) is free

        if (kt + 2 < KT) {
            const int sl = (kt + 2) % NST;
            uint32_t* da = dstA + sl * STAGE_WORDS;
            uint32_t* db = dstB + sl * STAGE_WORDS;
            size_t ko = (size_t)(kt + 2) * BK;
#pragma unroll
            for (int i = 0; i < 4; i++) cp_async16(da + i * 32 * PHW, srcA + ko + (size_t)i * 32 * K_DIM);
#pragma unroll
            for (int i = 0; i < 8; i++) cp_async16(db + i * 16 * PBF, srcB + ko + (size_t)i * 16 * K_DIM);
            cp_commit();
        }

        const uint32_t* Aw = smw + (kt % NST) * STAGE_WORDS;
        const float*    Bf = (const float*)(Aw + A_STAGE_WORDS);
#pragma unroll
        for (int ks2 = 0; ks2 < 2; ks2++) {    // two k16 steps per BK=32
            uint32_t a[4][4];
#pragma unroll
            for (int mi = 0; mi < 4; mi++) {
                int r = wm + mi * 16 + g;
                int base = ks2 * 8 + tc;
                a[mi][0] = Aw[r * PHW + base];
                a[mi][1] = Aw[(r + 8) * PHW + base];
                a[mi][2] = Aw[r * PHW + base + 4];
                a[mi][3] = Aw[(r + 8) * PHW + base + 4];
            }
            uint32_t b[8][2];
#pragma unroll
            for (int ni = 0; ni < 8; ni++) {
                int r = wn + ni * 8 + g;
                const float* bp = Bf + r * PBF + ks2 * 16 + 2 * tc;
                float2 p0 = *(const float2*)bp;
                float2 p1 = *(const float2*)(bp + 8);
                b[ni][0] = pack_f16x2(p0.x, p0.y);
                b[ni][1] = pack_f16x2(p1.x, p1.y);
            }
#pragma unroll
            for (int mi = 0; mi < 4; mi++)
#pragma unroll
                for (int ni = 0; ni < 8; ni++)
                    mma16(acc[mi][ni], a[mi], b[ni]);
        }
        // no bottom barrier: next iteration's top barrier orders buffer reuse
    }

    // write partial tile
    float* part = g_part + (size_t)z * (B_DIM * K_DIM);
#pragma unroll
    for (int mi = 0; mi < 4; mi++) {
#pragma unroll
        for (int ni = 0; ni < 8; ni++) {
            int gr = by * BM + wm + mi * 16 + g;
            int gc = bx * BN + wn + ni * 8 + tc * 2;
            size_t o0 = (size_t)gr * K_DIM + gc;
            size_t o2 = (size_t)(gr + 8) * K_DIM + gc;
            *(float2*)(part + o0) = make_float2(acc[mi][ni][0], acc[mi][ni][1]);
            *(float2*)(part + o2) = make_float2(acc[mi][ni][2], acc[mi][ni][3]);
        }
    }
}

// ---------------- reduce1: hn = tanh(sum of 4 partials + bih + bhh) ----------------

__global__ void __launch_bounds__(256)
reduce1_kernel(const float* __restrict__ bih, const float* __restrict__ bhh,
               float* __restrict__ hn_out) {
    size_t e = ((size_t)blockIdx.x * 256 + threadIdx.x) * 4;
    int col = (int)(e & (K_DIM - 1));
    float4 p0 = *(const float4*)(g_part + e);
    float4 p1 = *(const float4*)(g_part + (size_t)1 * B_DIM * K_DIM + e);
    float4 p2 = *(const float4*)(g_part + (size_t)2 * B_DIM * K_DIM + e);
    float4 p3 = *(const float4*)(g_part + (size_t)3 * B_DIM * K_DIM + e);
    float4 ba = *(const float4*)(bih + col);
    float4 bb = *(const float4*)(bhh + col);
    float t0 = tanhf(p0.x + p1.x + p2.x + p3.x + ba.x + bb.x);
    float t1 = tanhf(p0.y + p1.y + p2.y + p3.y + ba.y + bb.y);
    float t2 = tanhf(p0.z + p1.z + p2.z + p3.z + ba.z + bb.z);
    float t3 = tanhf(p0.w + p1.w + p2.w + p3.w + ba.w + bb.w);
    *(float4*)(hn_out + e) = make_float4(t0, t1, t2, t3);
    uint2 o;
    o.x = pack_f16x2(t0, t1);
    o.y = pack_f16x2(t2, t3);
    *(uint2*)(g_hn_h + e) = o;
}

// ---------------- softmax (fuses GEMM2 split-K reduce + bias) ----------------

#define SMT 512

__global__ void __launch_bounds__(SMT)
softmax_kernel(const float* __restrict__ blin, float* __restrict__ probs) {
    __shared__ float sl[K_DIM];
    __shared__ float red[SMT];
    const int row = blockIdx.x, tid = threadIdx.x;
    const size_t rb = (size_t)row * K_DIM;

    float m = -1e30f;
    for (int i = tid * 4; i < K_DIM; i += SMT * 4) {
        float4 p0 = *(const float4*)(g_part + rb + i);
        float4 p1 = *(const float4*)(g_part + (size_t)1 * B_DIM * K_DIM + rb + i);
        float4 p2 = *(const float4*)(g_part + (size_t)2 * B_DIM * K_DIM + rb + i);
        float4 p3 = *(const float4*)(g_part + (size_t)3 * B_DIM * K_DIM + rb + i);
        float4 b  = *(const float4*)(blin + i);
        float v0 = p0.x + p1.x + p2.x + p3.x + b.x;
        float v1 = p0.y + p1.y + p2.y + p3.y + b.y;
        float v2 = p0.z + p1.z + p2.z + p3.z + b.z;
        float v3 = p0.w + p1.w + p2.w + p3.w + b.w;
        *(float4*)(sl + i) = make_float4(v0, v1, v2, v3);
        m = fmaxf(m, fmaxf(fmaxf(v0, v1), fmaxf(v2, v3)));
    }
    red[tid] = m;
    __syncthreads();
    for (int s = SMT / 2; s > 0; s >>= 1) {
        if (tid < s) red[tid] = fmaxf(red[tid], red[tid + s]);
        __syncthreads();
    }
    m = red[0];
    __syncthreads();

    float sum = 0.0f;
    for (int i = tid; i < K_DIM; i += SMT) sum += expf(sl[i] - m);
    red[tid] = sum;
    __syncthreads();
    for (int s = SMT / 2; s > 0; s >>= 1) {
        if (tid < s) red[tid] += red[tid + s];
        __syncthreads();
    }
    float inv = 1.0f / red[0];

    for (int i = tid; i < K_DIM; i += SMT)
        probs[rb + i] = expf(sl[i] - m) * inv;
}

// ---------------- launch ----------------

extern "C" void kernel_launch(void* const* d_in, const int* in_sizes, int n_in,
                              void* d_out, int out_size) {
    const float* x    = (const float*)d_in[0];
    const float* h0   = (const float*)d_in[1];
    const float* wih  = (const float*)d_in[2];
    const float* bih  = (const float*)d_in[3];
    const float* whh  = (const float*)d_in[4];
    const float* bhh  = (const float*)d_in[5];
    const float* wlin = (const float*)d_in[6];
    const float* blin = (const float*)d_in[7];

    float* out = (float*)d_out;
    float* probs_out = out;
    float* hn_out    = out + (size_t)B_DIM * K_DIM;

    const int dyn = NST * STAGE_WORDS * sizeof(uint32_t);   // 92160 B (2 CTAs/SM)
    cudaFuncSetAttribute(gemm_splitk_kernel<1>, cudaFuncAttributeMaxDynamicSharedMemorySize, dyn);
    cudaFuncSetAttribute(gemm_splitk_kernel<2>, cudaFuncAttributeMaxDynamicSharedMemorySize, dyn);

    // convert x,h0 to fp16 once
    prep_kernel<<<(2 * B_DIM * K_DIM) / (256 * 4), 256>>>(x, h0);

    // GEMM1: partials of x@wih^T + h0@whh^T (fused K=8192, split 4, KT=64)
    dim3 grid1(K_DIM / BN, B_DIM / BM, SPLITK);    // (32,2,4) = 256 CTAs
    gemm_splitk_kernel<1><<<grid1, NTHREADS, dyn>>>(wih, whh, (K_DIM / 2) / BK);

    reduce1_kernel<<<(B_DIM * K_DIM) / (256 * 4), 256>>>(bih, bhh, hn_out);

    // GEMM2: partials of hn@wlin^T (K=4096, split 4, KT=32)
    dim3 grid2(K_DIM / BN, B_DIM / BM, SPLITK);    // (32,2,4) = 256 CTAs
    gemm_splitk_kernel<2><<<grid2, NTHREADS, dyn>>>(wlin, nullptr, (K_DIM / SPLITK) / BK);

    softmax_kernel<<<B_DIM, SMT>>>(blin, probs_out);
}

// round 17
// speedup vs baseline: 1.5101x; 1.0556x over previous
#include <cuda_runtime.h>
#include <cuda_fp16.h>
#include <stdint.h>
#include <math.h>

#define B_DIM 256
#define K_DIM 4096

#define BM 256              // full batch per CTA
#define BN 128
#define BK 64               // K elements per stage
#define PHW 36              // A row pitch in words (64 halves + pad) — conflict-free
#define PBF 72              // B row pitch in floats (64 floats + pad) — conflict-free
#define A_STAGE_WORDS (BM * PHW)                      // 9216 w (36864 B)
#define B_STAGE_WORDS (BN * PBF)                      // 9216 w (36864 B)
#define STAGE_WORDS (A_STAGE_WORDS + B_STAGE_WORDS)   // 18432 w (73728 B)
#define NST 3
#define NTHREADS 256
#define SPLITK1 4
#define SPLITK2 4

// scratch (allocation-free rule) — fp16 split-K partials
__device__ __half g_part_h[4 * B_DIM * K_DIM];  // 8 MB
__device__ __half g_xh_h[2 * B_DIM * K_DIM];    // fp16 [x ; h0]
__device__ __half g_hn_h[B_DIM * K_DIM];        // fp16 hidden state

// ---------------- helpers ----------------

__device__ __forceinline__ uint32_t pack_f16x2(float lo, float hi) {
    uint32_t d;
    asm("cvt.rn.f16x2.f32 %0, %1, %2;" : "=r"(d) : "f"(hi), "f"(lo));
    return d;
}

__device__ __forceinline__ float2 h2f2(uint32_t h) {
    __half2 v = *(__half2*)&h;
    return __half22float2(v);
}

__device__ __forceinline__ void mma16(float c[4], const uint32_t a[4], const uint32_t b[2]) {
    asm volatile(
        "mma.sync.aligned.m16n8k16.row.col.f32.f16.f16.f32 "
        "{%0,%1,%2,%3}, {%4,%5,%6,%7}, {%8,%9}, {%0,%1,%2,%3};\n"
        : "+f"(c[0]), "+f"(c[1]), "+f"(c[2]), "+f"(c[3])
        : "r"(a[0]), "r"(a[1]), "r"(a[2]), "r"(a[3]),
          "r"(b[0]), "r"(b[1]));
}

__device__ __forceinline__ void cp_async16(void* smem_dst, const void* gsrc) {
    unsigned s = (unsigned)__cvta_generic_to_shared(smem_dst);
    asm volatile("cp.async.cg.shared.global [%0], [%1], 16;\n" :: "r"(s), "l"(gsrc));
}
__device__ __forceinline__ void cp_commit() {
    asm volatile("cp.async.commit_group;\n");
}
template <int N>
__device__ __forceinline__ void cp_wait() {
    asm volatile("cp.async.wait_group %0;\n" :: "n"(N));
}

// ---------------- prep: convert x,h0 to fp16 once ----------------

__global__ void __launch_bounds__(256)
prep_kernel(const float* __restrict__ x, const float* __restrict__ h0) {
    size_t e = ((size_t)blockIdx.x * 256 + threadIdx.x) * 4;
    const size_t half_n = (size_t)B_DIM * K_DIM;
    const float* src = (e < half_n) ? (x + e) : (h0 + (e - half_n));
    float4 p = *(const float4*)src;
    uint2 o;
    o.x = pack_f16x2(p.x, p.y);
    o.y = pack_f16x2(p.z, p.w);
    *(uint2*)(g_xh_h + e) = o;
}

// ---------------- GEMM (split-K partial, fp16 HMMA, warp 64x64, NST=3 single-barrier) ----------------

template <int GEMM>
__global__ void __launch_bounds__(NTHREADS, 1)
gemm_splitk_kernel(const float* __restrict__ w0, const float* __restrict__ w1,
                   int KT) {
    extern __shared__ uint32_t smw[];   // 3 stages: [A 9216 w][B 9216 w]

    const int t = threadIdx.x;
    const int z = blockIdx.z;
    const int bx = blockIdx.x;

    // resolve split-K sources
    const __half* Ah;
    const float* Bw;
    size_t koff;
    if (GEMM == 1) {
        Ah = g_xh_h + (z >= 2 ? (size_t)B_DIM * K_DIM : 0);
        Bw = (z < 2) ? w0 : w1;
        koff = (size_t)(z & 1) * (K_DIM / 2);            // 2048
    } else {
        Ah = g_hn_h; Bw = w0;
        koff = (size_t)z * (K_DIM / SPLITK2);            // 1024
    }

    // load geometry
    // A: 2048 vec16/stage (256 rows x 8), 8 per thread; rows step +32
    const int arow = t >> 3, avc = t & 7;
    const __half* srcA = Ah + (size_t)arow * K_DIM + koff + avc * 8;
    uint32_t* dstA = smw + arow * PHW + avc * 4;
    // B: 2048 vec16/stage (128 rows x 16), 8 per thread; rows step +16
    const int brow = t >> 4, bvc = t & 15;
    const float* srcB = Bw + ((size_t)(bx * BN + brow)) * K_DIM + koff + bvc * 4;
    uint32_t* dstB = smw + A_STAGE_WORDS + brow * PBF + bvc * 4;

    float acc[4][8][4];
#pragma unroll
    for (int i = 0; i < 4; i++)
#pragma unroll
        for (int j = 0; j < 8; j++)
#pragma unroll
            for (int k = 0; k < 4; k++) acc[i][j][k] = 0.0f;

    const int lane = t & 31, warp = t >> 5;
    const int wm = (warp >> 1) * 64;    // 4 warps along M
    const int wn = (warp & 1) * 64;     // 2 warps along N (64 cols each)
    const int g = lane >> 2, tc = lane & 3;

    // prologue: stages 0,1
#pragma unroll
    for (int s = 0; s < 2; s++) {
        uint32_t* da = dstA + s * STAGE_WORDS;
        uint32_t* db = dstB + s * STAGE_WORDS;
        size_t ko = (size_t)s * BK;
#pragma unroll
        for (int i = 0; i < 8; i++) cp_async16(da + i * 32 * PHW, srcA + ko + (size_t)i * 32 * K_DIM);
#pragma unroll
        for (int i = 0; i < 8; i++) cp_async16(db + i * 16 * PBF, srcB + ko + (size_t)i * 16 * K_DIM);
        cp_commit();
    }

#pragma unroll 1
    for (int kt = 0; kt < KT; kt++) {
        if (kt + 1 < KT) cp_wait<1>(); else cp_wait<0>();
        __syncthreads();   // deposits visible; all warps done with compute kt-1

        if (kt + 2 < KT) {
            const int sl = (kt + 2) % NST;
            uint32_t* da = dstA + sl * STAGE_WORDS;
            uint32_t* db = dstB + sl * STAGE_WORDS;
            size_t ko = (size_t)(kt + 2) * BK;
#pragma unroll
            for (int i = 0; i < 8; i++) cp_async16(da + i * 32 * PHW, srcA + ko + (size_t)i * 32 * K_DIM);
#pragma unroll
            for (int i = 0; i < 8; i++) cp_async16(db + i * 16 * PBF, srcB + ko + (size_t)i * 16 * K_DIM);
            cp_commit();
        }

        const uint32_t* Aw = smw + (kt % NST) * STAGE_WORDS;
        const float*    Bf = (const float*)(Aw + A_STAGE_WORDS);
#pragma unroll
        for (int ks2 = 0; ks2 < 4; ks2++) {    // four k16 steps per BK=64
            uint32_t a[4][4];
#pragma unroll
            for (int mi = 0; mi < 4; mi++) {
                int r = wm + mi * 16 + g;
                int base = ks2 * 8 + tc;
                a[mi][0] = Aw[r * PHW + base];
                a[mi][1] = Aw[(r + 8) * PHW + base];
                a[mi][2] = Aw[r * PHW + base + 4];
                a[mi][3] = Aw[(r + 8) * PHW + base + 4];
            }
            uint32_t b[8][2];
#pragma unroll
            for (int ni = 0; ni < 8; ni++) {
                int r = wn + ni * 8 + g;
                const float* bp = Bf + r * PBF + ks2 * 16 + 2 * tc;
                float2 p0 = *(const float2*)bp;
                float2 p1 = *(const float2*)(bp + 8);
                b[ni][0] = pack_f16x2(p0.x, p0.y);
                b[ni][1] = pack_f16x2(p1.x, p1.y);
            }
#pragma unroll
            for (int mi = 0; mi < 4; mi++)
#pragma unroll
                for (int ni = 0; ni < 8; ni++)
                    mma16(acc[mi][ni], a[mi], b[ni]);
        }
        // no bottom barrier: next iteration's top barrier orders buffer reuse
    }

    // write partial tile as fp16 (halves partial DRAM traffic)
    __half* part = g_part_h + (size_t)z * (B_DIM * K_DIM);
#pragma unroll
    for (int mi = 0; mi < 4; mi++) {
#pragma unroll
        for (int ni = 0; ni < 8; ni++) {
            int gr = wm + mi * 16 + g;
            int gc = bx * BN + wn + ni * 8 + tc * 2;
            size_t o0 = (size_t)gr * K_DIM + gc;
            size_t o2 = (size_t)(gr + 8) * K_DIM + gc;
            *(uint32_t*)(part + o0) = pack_f16x2(acc[mi][ni][0], acc[mi][ni][1]);
            *(uint32_t*)(part + o2) = pack_f16x2(acc[mi][ni][2], acc[mi][ni][3]);
        }
    }
}

// ---------------- reduce1: hn = tanh(sum of 4 fp16 partials + bih + bhh) ----------------

__global__ void __launch_bounds__(256)
reduce1_kernel(const float* __restrict__ bih, const float* __restrict__ bhh,
               float* __restrict__ hn_out) {
    size_t e = ((size_t)blockIdx.x * 256 + threadIdx.x) * 4;
    int col = (int)(e & (K_DIM - 1));
    const size_t S = (size_t)B_DIM * K_DIM;
    uint2 q0 = *(const uint2*)(g_part_h + e);
    uint2 q1 = *(const uint2*)(g_part_h + S + e);
    uint2 q2 = *(const uint2*)(g_part_h + 2 * S + e);
    uint2 q3 = *(const uint2*)(g_part_h + 3 * S + e);
    float2 a0 = h2f2(q0.x), a1 = h2f2(q0.y);
    float2 b0 = h2f2(q1.x), b1 = h2f2(q1.y);
    float2 c0 = h2f2(q2.x), c1 = h2f2(q2.y);
    float2 d0 = h2f2(q3.x), d1 = h2f2(q3.y);
    float4 ba = *(const float4*)(bih + col);
    float4 bb = *(const float4*)(bhh + col);
    float t0 = tanhf(a0.x + b0.x + c0.x + d0.x + ba.x + bb.x);
    float t1 = tanhf(a0.y + b0.y + c0.y + d0.y + ba.y + bb.y);
    float t2 = tanhf(a1.x + b1.x + c1.x + d1.x + ba.z + bb.z);
    float t3 = tanhf(a1.y + b1.y + c1.y + d1.y + ba.w + bb.w);
    *(float4*)(hn_out + e) = make_float4(t0, t1, t2, t3);
    uint2 o;
    o.x = pack_f16x2(t0, t1);
    o.y = pack_f16x2(t2, t3);
    *(uint2*)(g_hn_h + e) = o;
}

// ---------------- softmax (fuses GEMM2 split-K reduce + bias) ----------------

#define SMT 512

__global__ void __launch_bounds__(SMT)
softmax_kernel(const float* __restrict__ blin, float* __restrict__ probs) {
    __shared__ float sl[K_DIM];
    __shared__ float red[SMT];
    const int row = blockIdx.x, tid = threadIdx.x;
    const size_t rb = (size_t)row * K_DIM;
    const size_t S = (size_t)B_DIM * K_DIM;

    float m = -1e30f;
    for (int i = tid * 4; i < K_DIM; i += SMT * 4) {
        uint2 q0 = *(const uint2*)(g_part_h + rb + i);
        uint2 q1 = *(const uint2*)(g_part_h + S + rb + i);
        uint2 q2 = *(const uint2*)(g_part_h + 2 * S + rb + i);
        uint2 q3 = *(const uint2*)(g_part_h + 3 * S + rb + i);
        float2 a0 = h2f2(q0.x), a1 = h2f2(q0.y);
        float2 b0 = h2f2(q1.x), b1 = h2f2(q1.y);
        float2 c0 = h2f2(q2.x), c1 = h2f2(q2.y);
        float2 d0 = h2f2(q3.x), d1 = h2f2(q3.y);
        float4 b = *(const float4*)(blin + i);
        float v0 = a0.x + b0.x + c0.x + d0.x + b.x;
        float v1 = a0.y + b0.y + c0.y + d0.y + b.y;
        float v2 = a1.x + b1.x + c1.x + d1.x + b.z;
        float v3 = a1.y + b1.y + c1.y + d1.y + b.w;
        *(float4*)(sl + i) = make_float4(v0, v1, v2, v3);
        m = fmaxf(m, fmaxf(fmaxf(v0, v1), fmaxf(v2, v3)));
    }
    red[tid] = m;
    __syncthreads();
    for (int s = SMT / 2; s > 0; s >>= 1) {
        if (tid < s) red[tid] = fmaxf(red[tid], red[tid + s]);
        __syncthreads();
    }
    m = red[0];
    __syncthreads();

    float sum = 0.0f;
    for (int i = tid; i < K_DIM; i += SMT) sum += expf(sl[i] - m);
    red[tid] = sum;
    __syncthreads();
    for (int s = SMT / 2; s > 0; s >>= 1) {
        if (tid < s) red[tid] += red[tid + s];
        __syncthreads();
    }
    float inv = 1.0f / red[0];

    for (int i = tid; i < K_DIM; i += SMT)
        probs[rb + i] = expf(sl[i] - m) * inv;
}

// ---------------- launch ----------------

extern "C" void kernel_launch(void* const* d_in, const int* in_sizes, int n_in,
                              void* d_out, int out_size) {
    const float* x    = (const float*)d_in[0];
    const float* h0   = (const float*)d_in[1];
    const float* wih  = (const float*)d_in[2];
    const float* bih  = (const float*)d_in[3];
    const float* whh  = (const float*)d_in[4];
    const float* bhh  = (const float*)d_in[5];
    const float* wlin = (const float*)d_in[6];
    const float* blin = (const float*)d_in[7];

    float* out = (float*)d_out;
    float* probs_out = out;
    float* hn_out    = out + (size_t)B_DIM * K_DIM;

    const int dyn = NST * STAGE_WORDS * sizeof(uint32_t);   // 221184 B
    cudaFuncSetAttribute(gemm_splitk_kernel<1>, cudaFuncAttributeMaxDynamicSharedMemorySize, dyn);
    cudaFuncSetAttribute(gemm_splitk_kernel<2>, cudaFuncAttributeMaxDynamicSharedMemorySize, dyn);

    // convert x,h0 to fp16 once
    prep_kernel<<<(2 * B_DIM * K_DIM) / (256 * 4), 256>>>(x, h0);

    // GEMM1: partials of x@wih^T + h0@whh^T (fused K=8192, split 4, KT=32)
    dim3 grid1(K_DIM / BN, 1, SPLITK1);    // (32,1,4) = 128 CTAs
    gemm_splitk_kernel<1><<<grid1, NTHREADS, dyn>>>(wih, whh, (K_DIM / 2) / BK);

    reduce1_kernel<<<(B_DIM * K_DIM) / (256 * 4), 256>>>(bih, bhh, hn_out);

    // GEMM2: partials of hn@wlin^T (K=4096, split 4, KT=16)
    dim3 grid2(K_DIM / BN, 1, SPLITK2);
    gemm_splitk_kernel<2><<<grid2, NTHREADS, dyn>>>(wlin, nullptr, (K_DIM / SPLITK2) / BK);

    softmax_kernel<<<B_DIM, SMT>>>(blin, probs_out);
}